// round 8
// baseline (speedup 1.0000x reference)
#include <cuda_runtime.h>
#include <math.h>
#include <stdint.h>

#define DIMD 512
#define HID  2048
#define NE   16
#define NB   8
#define NN   2048
#define CAP  256
#define NTOK (NB*NN)          // 16384
#define BC   (NB*CAP)         // 2048 rows per expert

// ---------------- device scratch ----------------
__device__ float          g_weights[NTOK*NE];
__device__ unsigned char  g_mask[NTOK*NE];
__device__ int            g_posE[NTOK*NE];
__device__ int            g_postok[NTOK];
__device__ float          g_proxy[NB*NE];
__device__ float          g_density[NB*NE];
__device__ float          g_ei[(size_t)NE*BC*DIMD];    // 64 MB (tf32 after cvt pass)
__device__ float          g_hidden[(size_t)NE*BC*HID]; // 256 MB (tf32, written by GEMM1)
__device__ float          g_eo[(size_t)NE*BC*DIMD];    // 64 MB (fp32)
__device__ float          g_w1c[(size_t)NE*DIMD*HID];  // 64 MB tf32 copy of w1
__device__ float          g_w2c[(size_t)NE*HID*DIMD];  // 64 MB tf32 copy of w2

__device__ __forceinline__ uint32_t f2tf32(float f)
{
    uint32_t u;
    asm("cvt.rna.tf32.f32 %0, %1;" : "=r"(u) : "f"(f));
    return u;
}

// ---------------- zero scratch ----------------
__global__ __launch_bounds__(256) void zero_kernel()
{
    size_t i = (size_t)blockIdx.x * 256 + threadIdx.x;
    float4* p = (float4*)g_ei;
    const size_t n4 = (size_t)NE*BC*DIMD/4;
    const size_t stride = (size_t)gridDim.x * 256;
    float4 z = make_float4(0.f,0.f,0.f,0.f);
    for (size_t j = i; j < n4; j += stride) p[j] = z;
    if (blockIdx.x == 0 && threadIdx.x < NB*NE) g_proxy[threadIdx.x] = 0.f;
}

// ---------------- convert weights to tf32 copies ----------------
__global__ __launch_bounds__(256) void wconv_kernel(const float* __restrict__ w1,
                                                    const float* __restrict__ w2)
{
    const size_t n = (size_t)NE*DIMD*HID;
    size_t i = (size_t)blockIdx.x * 256 + threadIdx.x;
    const size_t stride = (size_t)gridDim.x * 256;
    for (size_t j = i; j < n; j += stride) {
        ((uint32_t*)g_w1c)[j] = f2tf32(w1[j]);
        ((uint32_t*)g_w2c)[j] = f2tf32(w2[j]);
    }
}

// ---------------- convert g_ei in place to tf32 ----------------
__global__ __launch_bounds__(256) void eiconv_kernel()
{
    const size_t n = (size_t)NE*BC*DIMD;
    size_t i = (size_t)blockIdx.x * 256 + threadIdx.x;
    const size_t stride = (size_t)gridDim.x * 256;
    uint32_t* p = (uint32_t*)g_ei;
    for (size_t j = i; j < n; j += stride) p[j] = f2tf32(g_ei[j]);
}

// ---------------- gating ----------------
__global__ __launch_bounds__(256) void gating_kernel(const float* __restrict__ x,
                                                     const float* __restrict__ wg)
{
    __shared__ float s_wg[DIMD*NE];
    __shared__ float s_proxy[NE];
    int tid = threadIdx.x;
    for (int i = tid; i < DIMD*NE; i += 256) s_wg[i] = wg[i];
    if (tid < NE) s_proxy[tid] = 0.f;
    __syncthreads();

    int warp = tid >> 5, lane = tid & 31;
    int t = blockIdx.x * 8 + warp;
    const float* xr = x + (size_t)t * DIMD;

    float acc[NE];
    #pragma unroll
    for (int e = 0; e < NE; e++) acc[e] = 0.f;
    for (int d = lane; d < DIMD; d += 32) {
        float xv = xr[d];
        #pragma unroll
        for (int e = 0; e < NE; e++) acc[e] += xv * s_wg[d*NE + e];
    }
    #pragma unroll
    for (int e = 0; e < NE; e++) {
        #pragma unroll
        for (int off = 16; off; off >>= 1)
            acc[e] += __shfl_xor_sync(0xFFFFFFFFu, acc[e], off);
    }

    if (lane == 0) {
        float mx = acc[0];
        #pragma unroll
        for (int e = 1; e < NE; e++) mx = fmaxf(mx, acc[e]);
        float p[NE]; float sum = 0.f;
        #pragma unroll
        for (int e = 0; e < NE; e++) { p[e] = expf(acc[e] - mx); sum += p[e]; }
        float inv = 1.f / sum;
        #pragma unroll
        for (int e = 0; e < NE; e++) p[e] *= inv;

        float sv[NE]; int si[NE];
        #pragma unroll
        for (int i = 0; i < NE; i++) { sv[i] = p[i]; si[i] = i; }
        for (int i = 1; i < NE; i++) {
            float key = sv[i]; int ki = si[i];
            int j = i - 1;
            while (j >= 0 && sv[j] < key) { sv[j+1] = sv[j]; si[j+1] = si[j]; j--; }
            sv[j+1] = key; si[j+1] = ki;
        }
        float cum = 0.f; int k = NE;
        for (int i = 0; i < NE; i++) {
            cum += sv[i];
            if (cum >= 0.8f) { k = i + 1; break; }
        }
        float denom = 0.f;
        for (int i = 0; i < k; i++) denom += sv[i];
        float invd = 1.f / denom;

        #pragma unroll
        for (int e = 0; e < NE; e++) { g_mask[t*NE+e] = 0; g_weights[t*NE+e] = 0.f; }
        for (int i = 0; i < k; i++) {
            g_mask[t*NE + si[i]]    = 1;
            g_weights[t*NE + si[i]] = sv[i] * invd;
        }
        #pragma unroll
        for (int e = 0; e < NE; e++) atomicAdd(&s_proxy[e], p[e]);
    }
    __syncthreads();
    if (tid < NE) {
        int b = (blockIdx.x * 8) / NN;
        atomicAdd(&g_proxy[b*NE + tid], s_proxy[tid]);
    }
}

// ---------------- capacity scan ----------------
__global__ void scan_kernel()
{
    int be = blockIdx.x;
    int b = be / NE, e = be % NE;
    int lane = threadIdx.x;
    int running = 0;
    for (int n0 = 0; n0 < NN; n0 += 32) {
        int t = b * NN + n0 + lane;
        int m = g_mask[t*NE + e];
        unsigned bal = __ballot_sync(0xFFFFFFFFu, m);
        int pos = running + __popc(bal & ((1u << lane) - 1u));
        int valid = m && (pos < CAP);
        g_mask[t*NE + e] = (unsigned char)valid;
        g_posE[t*NE + e] = valid ? pos : 0;
        running += __popc(bal);
    }
    if (lane == 0) g_density[be] = (float)min(running, CAP) / (float)NN;
}

__global__ void postok_kernel()
{
    int t = blockIdx.x * 256 + threadIdx.x;
    if (t >= NTOK) return;
    int s = 0;
    #pragma unroll
    for (int e = 0; e < NE; e++) s += g_posE[t*NE + e];
    g_postok[t] = s;
}

__global__ void loss_kernel(float* __restrict__ out, int out_size)
{
    int tid = threadIdx.x;
    float v = (g_proxy[tid] * (1.0f / (float)NN)) * g_density[tid];
    #pragma unroll
    for (int off = 16; off; off >>= 1) v += __shfl_xor_sync(0xFFFFFFFFu, v, off);
    __shared__ float s[4];
    if ((tid & 31) == 0) s[tid >> 5] = v;
    __syncthreads();
    if (tid == 0) {
        float total = s[0] + s[1] + s[2] + s[3];
        float loss = total * (1.0f / 128.0f) * 256.0f * 0.01f;
        if (out_size > NTOK*DIMD) out[NTOK*DIMD] = loss;
    }
}

// ---------------- dispatch scatter ----------------
__global__ __launch_bounds__(128) void scatter_kernel(const float* __restrict__ x)
{
    int t = blockIdx.x;
    int tid = threadIdx.x;
    int pt = g_postok[t];
    if (pt >= CAP) return;
    int b = t >> 11;
    int row = b * CAP + pt;
    float4 xv = ((const float4*)(x + (size_t)t * DIMD))[tid];
    #pragma unroll
    for (int e = 0; e < NE; e++) {
        if (g_mask[t*NE + e]) {
            float* dst = g_ei + ((size_t)e * BC + row) * DIMD + tid * 4;
            atomicAdd(dst + 0, xv.x);
            atomicAdd(dst + 1, xv.y);
            atomicAdd(dst + 2, xv.z);
            atomicAdd(dst + 3, xv.w);
        }
    }
}

// ---------------- tf32 tensor-core batched GEMM, 3-stage cp.async ----------
// Operands already tf32-formatted. Block tile 128x128, BK=32, 8 warps, warp 64x32.

#define AS_STRIDE 36
#define BS_STRIDE 136
#define AS_TILE (128*AS_STRIDE)
#define BS_TILE (32*BS_STRIDE)
#define NSTAGE 3
#define GEMM_SMEM_BYTES (NSTAGE*(AS_TILE + BS_TILE)*4)

__device__ __forceinline__ void cp_async16(uint32_t smem_addr, const void* gptr)
{
    asm volatile("cp.async.cg.shared.global [%0], [%1], 16;\n"
                 :: "r"(smem_addr), "l"(gptr));
}
__device__ __forceinline__ void cp_commit()
{
    asm volatile("cp.async.commit_group;\n" ::: "memory");
}
__device__ __forceinline__ void cp_wait2()
{
    asm volatile("cp.async.wait_group 2;\n" ::: "memory");
}

__device__ __forceinline__ void mma_16x8x8(float c[4], const uint32_t a[4], const uint32_t b[2])
{
    asm volatile(
        "mma.sync.aligned.m16n8k8.row.col.f32.tf32.tf32.f32 "
        "{%0,%1,%2,%3}, {%4,%5,%6,%7}, {%8,%9}, {%0,%1,%2,%3};\n"
        : "+f"(c[0]), "+f"(c[1]), "+f"(c[2]), "+f"(c[3])
        : "r"(a[0]), "r"(a[1]), "r"(a[2]), "r"(a[3]), "r"(b[0]), "r"(b[1]));
}

template<bool APPLY_GELU, bool CVT_OUT>
__global__ __launch_bounds__(256) void gemm_tf32_db_kernel(const float* __restrict__ Ag,
                                                           const float* __restrict__ Bg,
                                                           float* __restrict__ Cg,
                                                           int M, int N, int K)
{
    extern __shared__ float smem[];
    float* As = smem;                         // [NSTAGE][128][AS_STRIDE]  ([m][k])
    float* Bs = smem + NSTAGE*AS_TILE;        // [NSTAGE][32][BS_STRIDE]   ([k][n])

    const float* A  = Ag + (size_t)blockIdx.z * M * K;
    const float* Bp = Bg + (size_t)blockIdx.z * K * N;
    float*       C  = Cg + (size_t)blockIdx.z * M * N;

    const int tid  = threadIdx.x;
    const int warp = tid >> 5, lane = tid & 31;
    const int wm = (warp & 1) * 64;
    const int wn = (warp >> 1) * 32;
    const int g  = lane >> 2, tg = lane & 3;

    const int bm = blockIdx.y * 128;
    const int bn = blockIdx.x * 128;

    const int aRow = tid >> 1;
    const int aCol = (tid & 1) * 16;
    const int bRow = tid >> 3;
    const int bCol = (tid & 7) * 16;

    const float* aSrc = A  + (size_t)(bm + aRow) * K + aCol;
    const float* bSrc = Bp + (size_t)bRow * N + bn + bCol;

    const uint32_t asBase = (uint32_t)__cvta_generic_to_shared(As);
    const uint32_t bsBase = (uint32_t)__cvta_generic_to_shared(Bs);
    const uint32_t aDst = asBase + (aRow*AS_STRIDE + aCol)*4;
    const uint32_t bDst = bsBase + (bRow*BS_STRIDE + bCol)*4;

    float c[4][4][4];
    #pragma unroll
    for (int mf = 0; mf < 4; mf++)
        #pragma unroll
        for (int nf = 0; nf < 4; nf++)
            #pragma unroll
            for (int r = 0; r < 4; r++) c[mf][nf][r] = 0.f;

    const int NT = K >> 5;

    // prefetch tiles 0 and 1
    #pragma unroll
    for (int v = 0; v < 4; v++) {
        cp_async16(aDst + v*16, aSrc + v*4);
        cp_async16(bDst + v*16, bSrc + v*4);
    }
    cp_commit();
    {
        const uint32_t aD = aDst + AS_TILE*4;
        const uint32_t bD = bDst + BS_TILE*4;
        const float* aS = aSrc + 32;
        const float* bS = bSrc + (size_t)32 * N;
        #pragma unroll
        for (int v = 0; v < 4; v++) {
            cp_async16(aD + v*16, aS + v*4);
            cp_async16(bD + v*16, bS + v*4);
        }
    }
    cp_commit();

    for (int it = 0; it < NT; it++) {
        const int cur = it % NSTAGE;
        if (it + 2 < NT) {
            const int nxt = (it + 2) % NSTAGE;
            const int kt = (it + 2) << 5;
            const uint32_t aD = aDst + nxt*AS_TILE*4;
            const uint32_t bD = bDst + nxt*BS_TILE*4;
            const float* aS = aSrc + kt;
            const float* bS = bSrc + (size_t)kt * N;
            #pragma unroll
            for (int v = 0; v < 4; v++) {
                cp_async16(aD + v*16, aS + v*4);
                cp_async16(bD + v*16, bS + v*4);
            }
        }
        cp_commit();
        cp_wait2();
        __syncthreads();

        const uint32_t* Asr = (const uint32_t*)(As + cur*AS_TILE);
        const uint32_t* Bsr = (const uint32_t*)(Bs + cur*BS_TILE);

        #pragma unroll
        for (int ks = 0; ks < 4; ks++) {
            const int k0 = ks * 8;
            uint32_t af[4][4];
            #pragma unroll
            for (int mf = 0; mf < 4; mf++) {
                const int m = wm + mf*16 + g;
                af[mf][0] = Asr[(m    )*AS_STRIDE + k0 + tg    ];
                af[mf][1] = Asr[(m + 8)*AS_STRIDE + k0 + tg    ];
                af[mf][2] = Asr[(m    )*AS_STRIDE + k0 + tg + 4];
                af[mf][3] = Asr[(m + 8)*AS_STRIDE + k0 + tg + 4];
            }
            uint32_t bf[4][2];
            #pragma unroll
            for (int nf = 0; nf < 4; nf++) {
                const int n = wn + nf*8 + g;
                bf[nf][0] = Bsr[(k0 + tg    )*BS_STRIDE + n];
                bf[nf][1] = Bsr[(k0 + tg + 4)*BS_STRIDE + n];
            }
            #pragma unroll
            for (int mf = 0; mf < 4; mf++)
                #pragma unroll
                for (int nf = 0; nf < 4; nf++)
                    mma_16x8x8(c[mf][nf], af[mf], bf[nf]);
        }
        __syncthreads();
    }

    // epilogue
    #pragma unroll
    for (int mf = 0; mf < 4; mf++) {
        const int row0 = bm + wm + mf*16 + g;
        #pragma unroll
        for (int nf = 0; nf < 4; nf++) {
            const int col = bn + wn + nf*8 + 2*tg;
            float v[4];
            #pragma unroll
            for (int r = 0; r < 4; r++) {
                float z = c[mf][nf][r];
                if (APPLY_GELU) z = 0.5f * z * (1.0f + erff(z * 0.70710678118654752f));
                if (CVT_OUT)    z = __uint_as_float(f2tf32(z));
                v[r] = z;
            }
            *(float2*)(C + (size_t)row0       * N + col) = make_float2(v[0], v[1]);
            *(float2*)(C + (size_t)(row0 + 8) * N + col) = make_float2(v[2], v[3]);
        }
    }
}

// ---------------- combine ----------------
__global__ __launch_bounds__(128) void combine_kernel(float* __restrict__ out)
{
    int t = blockIdx.x;
    int tid = threadIdx.x;
    float4 acc = make_float4(0.f, 0.f, 0.f, 0.f);
    int pt = g_postok[t];
    if (pt < CAP) {
        int b = t >> 11;
        int row = b * CAP + pt;
        #pragma unroll
        for (int e = 0; e < NE; e++) {
            if (g_mask[t*NE + e]) {
                float w = g_weights[t*NE + e];
                float4 v = ((const float4*)(g_eo + ((size_t)e * BC + row) * DIMD))[tid];
                acc.x += w * v.x; acc.y += w * v.y; acc.z += w * v.z; acc.w += w * v.w;
            }
        }
    }
    ((float4*)(out + (size_t)t * DIMD))[tid] = acc;
}

// ---------------- launch ----------------
extern "C" void kernel_launch(void* const* d_in, const int* in_sizes, int n_in,
                              void* d_out, int out_size)
{
    const float* x  = nullptr;
    const float* wg = nullptr;
    const float* w1 = nullptr;
    const float* w2 = nullptr;
    for (int i = 0; i < n_in; i++) {
        int sz = in_sizes[i];
        const float* p = (const float*)d_in[i];
        if (sz == NTOK*DIMD)            { x = p; }
        else if (sz == DIMD*NE)         { wg = p; }
        else if (sz == NE*DIMD*HID)     { if (!w1) w1 = p; else w2 = p; }
    }
    if (!x || !wg || !w1 || !w2) {
        x  = (const float*)d_in[0];
        wg = (const float*)d_in[1];
        w1 = (const float*)d_in[2];
        w2 = (const float*)d_in[3];
    }
    float* out = (float*)d_out;

    static float* p_ei = nullptr;
    static float* p_hidden = nullptr;
    static float* p_eo = nullptr;
    static float* p_w1c = nullptr;
    static float* p_w2c = nullptr;
    if (!p_ei) {
        cudaGetSymbolAddress((void**)&p_ei,     g_ei);
        cudaGetSymbolAddress((void**)&p_hidden, g_hidden);
        cudaGetSymbolAddress((void**)&p_eo,     g_eo);
        cudaGetSymbolAddress((void**)&p_w1c,    g_w1c);
        cudaGetSymbolAddress((void**)&p_w2c,    g_w2c);
        cudaFuncSetAttribute((const void*)gemm_tf32_db_kernel<true,true>,
                             cudaFuncAttributeMaxDynamicSharedMemorySize, GEMM_SMEM_BYTES);
        cudaFuncSetAttribute((const void*)gemm_tf32_db_kernel<false,false>,
                             cudaFuncAttributeMaxDynamicSharedMemorySize, GEMM_SMEM_BYTES);
    }

    zero_kernel<<<2048, 256>>>();
    wconv_kernel<<<2048, 256>>>(w1, w2);
    gating_kernel<<<NTOK/8, 256>>>(x, wg);
    scan_kernel<<<NB*NE, 32>>>();
    postok_kernel<<<NTOK/256, 256>>>();
    scatter_kernel<<<NTOK, 128>>>(x);
    eiconv_kernel<<<2048, 256>>>();

    // GEMM1 + GELU (output pre-converted to tf32): [BC x DIMD] @ [DIMD x HID]
    gemm_tf32_db_kernel<true,true ><<<dim3(HID/128, BC/128, NE), 256, GEMM_SMEM_BYTES>>>(p_ei, p_w1c, p_hidden, BC, HID, DIMD);
    // GEMM2: [BC x HID] @ [HID x DIMD]
    gemm_tf32_db_kernel<false,false><<<dim3(DIMD/128, BC/128, NE), 256, GEMM_SMEM_BYTES>>>(p_hidden, p_w2c, p_eo, BC, DIMD, HID);

    combine_kernel<<<NTOK, 128>>>(out);
    loss_kernel<<<1, 128>>>(out, out_size);
}